// round 12
// baseline (speedup 1.0000x reference)
#include <cuda_runtime.h>
#include <cstdint>
#include <cstddef>

// Fixed problem shapes
#define MROWS  8192           // B*S
#define INDIM  4096
#define OUTDIM 4096
#define RANK   8
#define NTHR   256            // 8 warps per CTA, 2 CTAs per SM
#define TROWS  32             // rows per tile (lane = row)
#define NTILE  (MROWS/TROWS)  // 256
#define ICH    128            // i-chunk size
#define NCH    (INDIM/ICH)    // 32
#define NBUF   5              // pipeline depth (4 chunks in flight)
#define XSTR   132            // padded row stride in smem floats (conflict-free)
#define XBUF   (TROWS*XSTR)   // 4224 floats per x buffer

// smem layout (float offsets)
#define S_X    0                              // 5 x 4224 = 21120
#define S_RED  (NBUF*XBUF)                    // 21120: 8 warps x 32 rows x 8
#define S_INT  (S_RED + 8*TROWS*RANK)         // 23168: 32 x 8
#define S_TOT  (S_INT + TROWS*RANK)           // 23424 floats
#define SMEM_BYTES (S_TOT*4)                  // 93696 B (2 CTAs = 187 KB/SM)

__constant__ float c_nf4[16] = {
    -1.0f, -0.6961928009986877f, -0.5250730514526367f, -0.39491748809814453f,
    -0.28444138169288635f, -0.18477343022823334f, -0.09105003625154495f, 0.0f,
    0.07958029955625534f, 0.16093020141124725f, 0.24611230194568634f,
    0.33791524171829224f, 0.44070982933044434f, 0.5626170039176941f,
    0.7229568362236328f, 1.0f};

// Pre-dequantized weights (scratch __device__ globals; L2/L1-resident)
__device__ __align__(16) float g_WA[RANK * INDIM];    // [r][i]
__device__ __align__(16) float g_WBt[RANK * OUTDIM];  // [r][o], pre-scaled by 4.0

// Single merged dequant kernel (one launch)
__global__ void dequant_kernel(const int* __restrict__ codesA,
                               const float* __restrict__ absmaxA,
                               const int* __restrict__ codesB,
                               const float* __restrict__ absmaxB) {
    int i = blockIdx.x * blockDim.x + threadIdx.x;
    if (i < RANK * INDIM) {
        g_WA[i] = c_nf4[codesA[i] & 15] * absmaxA[i >> 6];
    } else {
        int j = i - RANK * INDIM;
        if (j < OUTDIM * RANK) {
            int o = j >> 3, r = j & 7;
            g_WBt[r * OUTDIM + o] = 4.0f * c_nf4[codesB[j] & 15] * absmaxB[j >> 6];
        }
    }
}

__device__ __forceinline__ void cp_async16(uint32_t saddr, const void* gptr) {
    asm volatile("cp.async.cg.shared.global [%0], [%1], 16;\n"
                 :: "r"(saddr), "l"(gptr));
}
__device__ __forceinline__ void fma2(unsigned long long& d,
                                     unsigned long long a, unsigned long long b) {
    asm("fma.rn.f32x2 %0, %1, %2, %0;" : "+l"(d) : "l"(a), "l"(b));
}
__device__ __forceinline__ unsigned long long pk2(float v) {
    unsigned long long r; asm("mov.b64 %0, {%1, %1};" : "=l"(r) : "f"(v)); return r;
}
__device__ __forceinline__ unsigned long long pkab(float a, float b) {
    unsigned long long r; asm("mov.b64 %0, {%1, %2};" : "=l"(r) : "f"(a), "f"(b)); return r;
}
__device__ __forceinline__ float2 unpk(unsigned long long v) {
    float2 f; asm("mov.b64 {%0, %1}, %2;" : "=f"(f.x), "=f"(f.y) : "l"(v)); return f;
}

// Producer for linear chunk L: per-thread cp.async, x only (1024 float4, 4/thread)
__device__ __forceinline__ void issue_chunk(
    uint32_t smb, const float* __restrict__ x,
    int t0, int grid, int L, int tid)
{
    int tile = t0 + (L >> 5) * grid;
    if (tile >= NTILE) return;
    int ch = L & 31;
    int bb = L % NBUF;
    const float* src = x + (size_t)tile * TROWS * INDIM + (size_t)ch * ICH;
    #pragma unroll
    for (int k = 0; k < 4; k++) {
        int idx = tid + k * NTHR;
        int row = idx >> 5, c4 = idx & 31;
        cp_async16(smb + (uint32_t)((S_X + bb * XBUF + row * XSTR + c4 * 4) * 4),
                   src + (size_t)row * INDIM + c4 * 4);
    }
}

__global__ void __launch_bounds__(NTHR, 2)
qlora_kernel(const float* __restrict__ x, float* __restrict__ out)
{
    extern __shared__ float sm[];
    const int tid = threadIdx.x, lane = tid & 31, wid = tid >> 5;
    const int grid = gridDim.x;
    const int t0 = blockIdx.x;
    if (t0 >= NTILE) return;               // surplus CTAs exit immediately

    uint32_t smb = (uint32_t)__cvta_generic_to_shared(sm);

    // prologue: chunks 0..3 into buffers 0..3, one commit group each
    #pragma unroll
    for (int L = 0; L < NBUF - 1; L++) {
        issue_chunk(smb, x, t0, grid, L, tid);
        asm volatile("cp.async.commit_group;\n" ::: "memory");
    }

    int q = 0;           // next chunk to consume
    int Lh = NBUF - 1;   // next chunk to issue
    int cbuf = 0;        // consumer buffer index (q % NBUF)

    for (int t = t0; t < NTILE; t += grid) {
        unsigned long long a01[RANK], a23[RANK];
        #pragma unroll
        for (int r = 0; r < RANK; r++) { a01[r] = 0ull; a23[r] = 0ull; }

        #pragma unroll 1
        for (int c = 0; c < NCH; c++) {
            asm volatile("cp.async.wait_group 3;\n" ::: "memory");
            __syncthreads();   // chunk q visible; readers of q-1 retired

            issue_chunk(smb, x, t0, grid, Lh, tid);  // into buffer (q-1)%5
            asm volatile("cp.async.commit_group;\n" ::: "memory");
            Lh++;

            // consume chunk q: lane = row; warp w covers i in [w*16, w*16+16)
            const ulonglong2* xp =
                (const ulonglong2*)(sm + S_X + cbuf * XBUF + lane * XSTR) + wid * 4;
            const ulonglong2* __restrict__ wp =
                (const ulonglong2*)(g_WA + c * ICH) + wid * 4;   // uniform, L1-hit
            #pragma unroll
            for (int j = 0; j < 4; j++) {
                ulonglong2 xv = xp[j];                 // conflict-free LDS.128
                ulonglong2 wv[RANK];
                #pragma unroll
                for (int r = 0; r < RANK; r++)
                    wv[r] = wp[r * (INDIM / 4) + j];   // uniform LDG.128
                #pragma unroll
                for (int r = 0; r < RANK; r++) {
                    fma2(a01[r], xv.x, wv[r].x);
                    fma2(a23[r], xv.y, wv[r].y);
                }
            }
            q++;
            cbuf = (cbuf + 1 == NBUF) ? 0 : cbuf + 1;
        }

        // cross-warp reduce: 8 warp partials per (row, r)
        {
            float v[RANK];
            #pragma unroll
            for (int r = 0; r < RANK; r++) {
                float2 p = unpk(a01[r]); float2 qq = unpk(a23[r]);
                v[r] = (p.x + p.y) + (qq.x + qq.y);
            }
            float4* dst = (float4*)(sm + S_RED + wid * (TROWS * RANK) + lane * RANK);
            dst[0] = make_float4(v[0], v[1], v[2], v[3]);
            dst[1] = make_float4(v[4], v[5], v[6], v[7]);
        }
        __syncthreads();
        {
            float s = 0.0f;     // all 256 threads: tid = row*8 + r
            #pragma unroll
            for (int w2 = 0; w2 < 8; w2++)
                s += sm[S_RED + w2 * (TROWS * RANK) + tid];
            sm[S_INT + tid] = s;
        }
        __syncthreads();

        // epilogue: thread owns 4 float4 col groups; W_B from L2/L1 (pre-scaled)
        {
            size_t outbase = (size_t)t * TROWS * OUTDIM;
            const float4* gWB4 = (const float4*)g_WBt;
            #pragma unroll
            for (int og = 0; og < 4; og++) {
                int g = tid + og * NTHR;
                unsigned long long wb01[RANK], wb23[RANK];
                #pragma unroll
                for (int r = 0; r < RANK; r++) {
                    float4 w = __ldg(gWB4 + r * (OUTDIM / 4) + g);
                    wb01[r] = pkab(w.x, w.y);
                    wb23[r] = pkab(w.z, w.w);
                }
                #pragma unroll 4
                for (int m = 0; m < TROWS; m++) {
                    const float4* ip = (const float4*)(sm + S_INT) + m * 2;
                    float4 s0 = ip[0], s1 = ip[1];   // broadcast LDS
                    float sv[RANK] = { s0.x, s0.y, s0.z, s0.w,
                                       s1.x, s1.y, s1.z, s1.w };
                    unsigned long long o01 = 0ull, o23 = 0ull;
                    #pragma unroll
                    for (int r = 0; r < RANK; r++) {
                        unsigned long long s2 = pk2(sv[r]);
                        fma2(o01, s2, wb01[r]);
                        fma2(o23, s2, wb23[r]);
                    }
                    ulonglong2 ov; ov.x = o01; ov.y = o23;
                    *(ulonglong2*)(out + outbase + (size_t)m * OUTDIM + g * 4) = ov;
                }
            }
        }
    }
}

extern "C" void kernel_launch(void* const* d_in, const int* in_sizes, int n_in,
                              void* d_out, int out_size) {
    const float* x        = (const float*)d_in[0];
    const int*   codes_A  = (const int*)d_in[1];
    const float* absmax_A = (const float*)d_in[2];
    const int*   codes_B  = (const int*)d_in[3];
    const float* absmax_B = (const float*)d_in[4];
    float*       out      = (float*)d_out;
    (void)in_sizes; (void)n_in; (void)out_size;

    // single dequant launch covering both A (32768) and B (32768)
    dequant_kernel<<<(2 * RANK * INDIM + 255) / 256, 256>>>(
        codes_A, absmax_A, codes_B, absmax_B);

    int dev = 0, nsm = 148;
    cudaGetDevice(&dev);
    cudaDeviceGetAttribute(&nsm, cudaDevAttrMultiProcessorCount, dev);
    int grid = 2 * nsm;   // 2 CTAs/SM; 256 working CTAs finish in one wave

    cudaFuncSetAttribute(qlora_kernel,
                         cudaFuncAttributeMaxDynamicSharedMemorySize, SMEM_BYTES);
    qlora_kernel<<<grid, NTHR, SMEM_BYTES>>>(x, out);
}

// round 13
// speedup vs baseline: 1.4256x; 1.4256x over previous
#include <cuda_runtime.h>
#include <cstdint>
#include <cstddef>

// Fixed problem shapes
#define MROWS  8192           // B*S
#define INDIM  4096
#define OUTDIM 4096
#define RANK   8
#define NTHR   256            // 8 warps per CTA, 2 CTAs per SM (reg-limited)
#define TROWS  32             // rows per tile; warp owns 4 rows
#define NTILE  (MROWS/TROWS)  // 256
#define NC     32             // i-chunks of 128 floats (lane owns 4 i per chunk)

__constant__ float c_nf4[16] = {
    -1.0f, -0.6961928009986877f, -0.5250730514526367f, -0.39491748809814453f,
    -0.28444138169288635f, -0.18477343022823334f, -0.09105003625154495f, 0.0f,
    0.07958029955625534f, 0.16093020141124725f, 0.24611230194568634f,
    0.33791524171829224f, 0.44070982933044434f, 0.5626170039176941f,
    0.7229568362236328f, 1.0f};

// Pre-dequantized weights (scratch __device__ globals; L1/L2-resident)
__device__ __align__(16) float g_WA[RANK * INDIM];    // [r][i]
__device__ __align__(16) float g_WBt[RANK * OUTDIM];  // [r][o], pre-scaled by 4.0

// Single merged dequant kernel (one launch; proven in R10)
__global__ void dequant_kernel(const int* __restrict__ codesA,
                               const float* __restrict__ absmaxA,
                               const int* __restrict__ codesB,
                               const float* __restrict__ absmaxB) {
    int i = blockIdx.x * blockDim.x + threadIdx.x;
    if (i < RANK * INDIM) {
        g_WA[i] = c_nf4[codesA[i] & 15] * absmaxA[i >> 6];
    } else {
        int j = i - RANK * INDIM;
        if (j < OUTDIM * RANK) {
            int o = j >> 3, r = j & 7;
            g_WBt[r * OUTDIM + o] = 4.0f * c_nf4[codesB[j] & 15] * absmaxB[j >> 6];
        }
    }
}

__device__ __forceinline__ void fma2(unsigned long long& d,
                                     unsigned long long a, unsigned long long b) {
    asm("fma.rn.f32x2 %0, %1, %2, %0;" : "+l"(d) : "l"(a), "l"(b));
}
__device__ __forceinline__ unsigned long long pk2(float v) {
    unsigned long long r; asm("mov.b64 %0, {%1, %1};" : "=l"(r) : "f"(v)); return r;
}
__device__ __forceinline__ unsigned long long pkab(float a, float b) {
    unsigned long long r; asm("mov.b64 %0, {%1, %2};" : "=l"(r) : "f"(a), "f"(b)); return r;
}
__device__ __forceinline__ float2 unpk(unsigned long long v) {
    float2 f; asm("mov.b64 {%0, %1}, %2;" : "=f"(f.x), "=f"(f.y) : "l"(v)); return f;
}
// 16B streaming load (evict-first: protect L1 for the weights)
__device__ __forceinline__ ulonglong2 ldcs16(const void* p) {
    ulonglong2 v;
    asm volatile("ld.global.cs.v2.u64 {%0, %1}, [%2];"
                 : "=l"(v.x), "=l"(v.y) : "l"(p));
    return v;
}
// 16B read-only cached load
__device__ __forceinline__ ulonglong2 ldg16(const void* p) {
    ulonglong2 v;
    asm volatile("ld.global.nc.v2.u64 {%0, %1}, [%2];"
                 : "=l"(v.x), "=l"(v.y) : "l"(p));
    return v;
}

__global__ void __launch_bounds__(NTHR, 2)
qlora_kernel(const float* __restrict__ x, float* __restrict__ out)
{
    __shared__ float sInt[TROWS * RANK];   // interm[row][r]
    const int tid = threadIdx.x, lane = tid & 31, wid = tid >> 5;
    const int tile = blockIdx.x;

    // ---- phase 1: warp owns rows 4*wid..+3; lane owns i = 4*lane + 128*c ----
    // x row pointers (16B slice per (row, chunk) per lane; fully thread-local)
    const char* xr0 = (const char*)(x + ((size_t)tile * TROWS + wid * 4) * INDIM
                                      + 4 * lane);
    const char* xr1 = xr0 + INDIM * 4;
    const char* xr2 = xr1 + INDIM * 4;
    const char* xr3 = xr2 + INDIM * 4;

    // accumulators: (even-i, odd-i) partial sums per (row m, rank r)
    unsigned long long acc[4][RANK];
    #pragma unroll
    for (int m = 0; m < 4; m++)
        #pragma unroll
        for (int r = 0; r < RANK; r++) acc[m][r] = 0ull;

    const ulonglong2* __restrict__ wa = (const ulonglong2*)g_WA;  // [r][i/4] 16B units
    const int wl = lane;   // lane offset in 16B units within a chunk

    ulonglong2 xa[4], xb[4];
    xa[0] = ldcs16(xr0); xa[1] = ldcs16(xr1);
    xa[2] = ldcs16(xr2); xa[3] = ldcs16(xr3);

    #pragma unroll 1
    for (int c = 0; c < NC; c += 2) {
        // prefetch chunk c+1 (always valid: c <= 30)
        {
            int off = (c + 1) * 512;   // 128 floats = 512 B
            xb[0] = ldcs16(xr0 + off); xb[1] = ldcs16(xr1 + off);
            xb[2] = ldcs16(xr2 + off); xb[3] = ldcs16(xr3 + off);
        }
        // compute chunk c with xa
        #pragma unroll
        for (int r = 0; r < RANK; r++) {
            ulonglong2 wv = ldg16(wa + (size_t)r * (INDIM / 4) + c * 32 + wl);
            #pragma unroll
            for (int m = 0; m < 4; m++) {
                fma2(acc[m][r], xa[m].x, wv.x);
                fma2(acc[m][r], xa[m].y, wv.y);
            }
        }
        // prefetch chunk c+2 into xa (guarded at the tail)
        if (c + 2 < NC) {
            int off = (c + 2) * 512;
            xa[0] = ldcs16(xr0 + off); xa[1] = ldcs16(xr1 + off);
            xa[2] = ldcs16(xr2 + off); xa[3] = ldcs16(xr3 + off);
        }
        // compute chunk c+1 with xb
        #pragma unroll
        for (int r = 0; r < RANK; r++) {
            ulonglong2 wv = ldg16(wa + (size_t)r * (INDIM / 4) + (c + 1) * 32 + wl);
            #pragma unroll
            for (int m = 0; m < 4; m++) {
                fma2(acc[m][r], xb[m].x, wv.x);
                fma2(acc[m][r], xb[m].y, wv.y);
            }
        }
    }

    // ---- warp-local reduction: horizontal add + butterfly over 32 lanes ----
    float v[4][RANK];
    #pragma unroll
    for (int m = 0; m < 4; m++)
        #pragma unroll
        for (int r = 0; r < RANK; r++) {
            float2 p = unpk(acc[m][r]);
            float s = p.x + p.y;
            s += __shfl_xor_sync(0xffffffffu, s, 16);
            s += __shfl_xor_sync(0xffffffffu, s, 8);
            s += __shfl_xor_sync(0xffffffffu, s, 4);
            s += __shfl_xor_sync(0xffffffffu, s, 2);
            s += __shfl_xor_sync(0xffffffffu, s, 1);
            v[m][r] = s;
        }
    if (lane == 0) {
        #pragma unroll
        for (int m = 0; m < 4; m++) {
            float4* dst = (float4*)(sInt + (wid * 4 + m) * RANK);
            dst[0] = make_float4(v[m][0], v[m][1], v[m][2], v[m][3]);
            dst[1] = make_float4(v[m][4], v[m][5], v[m][6], v[m][7]);
        }
    }
    __syncthreads();

    // ---- phase 2 epilogue (R10-proven): thread owns 4 float4 col groups ----
    {
        size_t outbase = (size_t)tile * TROWS * OUTDIM;
        const float4* gWB4 = (const float4*)g_WBt;
        #pragma unroll
        for (int og = 0; og < 4; og++) {
            int g = tid + og * NTHR;
            unsigned long long wb01[RANK], wb23[RANK];
            #pragma unroll
            for (int r = 0; r < RANK; r++) {
                float4 w = __ldg(gWB4 + r * (OUTDIM / 4) + g);
                wb01[r] = pkab(w.x, w.y);
                wb23[r] = pkab(w.z, w.w);
            }
            #pragma unroll 4
            for (int m = 0; m < TROWS; m++) {
                const float4* ip = (const float4*)sInt + m * 2;
                float4 s0 = ip[0], s1 = ip[1];   // broadcast LDS
                float sv[RANK] = { s0.x, s0.y, s0.z, s0.w,
                                   s1.x, s1.y, s1.z, s1.w };
                unsigned long long o01 = 0ull, o23 = 0ull;
                #pragma unroll
                for (int r = 0; r < RANK; r++) {
                    unsigned long long s2 = pk2(sv[r]);
                    fma2(o01, s2, wb01[r]);
                    fma2(o23, s2, wb23[r]);
                }
                ulonglong2 ov; ov.x = o01; ov.y = o23;
                *(ulonglong2*)(out + outbase + (size_t)m * OUTDIM + g * 4) = ov;
            }
        }
    }
}

extern "C" void kernel_launch(void* const* d_in, const int* in_sizes, int n_in,
                              void* d_out, int out_size) {
    const float* x        = (const float*)d_in[0];
    const int*   codes_A  = (const int*)d_in[1];
    const float* absmax_A = (const float*)d_in[2];
    const int*   codes_B  = (const int*)d_in[3];
    const float* absmax_B = (const float*)d_in[4];
    float*       out      = (float*)d_out;
    (void)in_sizes; (void)n_in; (void)out_size;

    // single dequant launch covering both A (32768) and B (32768)
    dequant_kernel<<<(2 * RANK * INDIM + 255) / 256, 256>>>(
        codes_A, absmax_A, codes_B, absmax_B);

    // one CTA per tile; 2 CTAs co-resident per SM (register-limited)
    qlora_kernel<<<NTILE, NTHR>>>(x, out);
}